// round 4
// baseline (speedup 1.0000x reference)
#include <cuda_runtime.h>
#include <cuda_bf16.h>

// Chamfer distance matrix, B=32, G=64, N=32, C=3.
// R4: occupancy push. Per-warp tile halved to j=2 g2-pairs (16 min
// accumulators) so persistent regs fit under __launch_bounds__(256,3)
// (<=85 regs) -> 24 warps/SM instead of 16. Block covers (b, g1-pair,
// g2-half): grid 2048, smem ~17.5KB. Packed FFMA2 math as R3, lane-owned
// operands pre-scaled by -2.

#define NP 32

typedef unsigned long long u64;

static __device__ __forceinline__ u64 pack2(float lo, float hi) {
    u64 r; asm("mov.b64 %0, {%1, %2};" : "=l"(r) : "f"(lo), "f"(hi)); return r;
}
static __device__ __forceinline__ float2 unpack2(u64 v) {
    float2 f; asm("mov.b64 {%0, %1}, %2;" : "=f"(f.x), "=f"(f.y) : "l"(v)); return f;
}
static __device__ __forceinline__ u64 fma2(u64 a, u64 b, u64 c) {
    u64 d; asm("fma.rn.f32x2 %0, %1, %2, %3;" : "=l"(d) : "l"(a), "l"(b), "l"(c)); return d;
}
static __device__ __forceinline__ u64 mul2(u64 a, u64 b) {
    u64 d; asm("mul.rn.f32x2 %0, %1, %2;" : "=l"(d) : "l"(a), "l"(b)); return d;
}

__global__ __launch_bounds__(256, 3)
void chamfer_matrix_kernel(const float* __restrict__ x1,
                           const float* __restrict__ x2,
                           float* __restrict__ out)
{
    // Pair-packed x2 subset (16 g2-pairs = this block's g2-half):
    //   s2a[p*32+m] = {a.x,b.x, a.y,b.y}; s2b[p*32+m] = {a.z,b.z, a.w,b.w}
    __shared__ ulonglong2 s2a[16 * NP];   // 8 KB
    __shared__ ulonglong2 s2b[16 * NP];   // 8 KB
    __shared__ float4 s1A[NP];
    __shared__ float4 s1B[NP];

    const int blk  = blockIdx.x;        // b*64 + gp*2 + half
    const int b    = blk >> 6;
    const int gp   = (blk >> 1) & 31;   // g1 pair -> groups 2gp, 2gp+1
    const int half = blk & 1;           // g2 half -> groups [half*32, half*32+32)
    const int tid  = threadIdx.x;

    // Stage this block's 512 x2 points, pre-packed pairwise.
    const float* __restrict__ x2b = x2 + (size_t)(b * 64 + half * 32) * NP * 3;
    #pragma unroll
    for (int i = tid; i < 16 * 2 * NP; i += 256) {
        const float X = x2b[i * 3 + 0];
        const float Y = x2b[i * 3 + 1];
        const float Z = x2b[i * 3 + 2];
        const float W = fmaf(X, X, fmaf(Y, Y, Z * Z));
        const int g = i >> 5, m = i & 31;      // g = local group 0..31
        const int p = g >> 1, h = g & 1;       // p = local pair 0..15
        float* da = (float*)&s2a[p * NP + m];
        float* db = (float*)&s2b[p * NP + m];
        da[0 + h] = X;  da[2 + h] = Y;
        db[0 + h] = Z;  db[2 + h] = W;
    }
    // Stage the two x1 groups.
    if (tid < 2 * NP) {
        const int h = tid >> 5, m = tid & 31;
        const float* __restrict__ p = x1 + (size_t)((b * 64 + 2 * gp + h) * NP + m) * 3;
        const float X = p[0], Y = p[1], Z = p[2];
        const float4 v = make_float4(X, Y, Z, fmaf(X, X, fmaf(Y, Y, Z * Z)));
        if (h == 0) s1A[m] = v; else s1B[m] = v;
    }
    __syncthreads();

    const int wid  = tid >> 5;
    const int lane = tid & 31;

    const float4 p1A = s1A[lane];
    const float4 p1B = s1B[lane];
    // Pre-scaled (-2x) splats for dir-1 dots.
    const u64 pxA = pack2(-2.0f * p1A.x, -2.0f * p1A.x);
    const u64 pyA = pack2(-2.0f * p1A.y, -2.0f * p1A.y);
    const u64 pzA = pack2(-2.0f * p1A.z, -2.0f * p1A.z);
    const u64 pxB = pack2(-2.0f * p1B.x, -2.0f * p1B.x);
    const u64 pyB = pack2(-2.0f * p1B.y, -2.0f * p1B.y);
    const u64 pzB = pack2(-2.0f * p1B.z, -2.0f * p1B.z);

    // Each warp owns 2 local g2-pairs (wid*2, wid*2+1).
    const u64 neg2 = pack2(-2.0f, -2.0f);
    const ulonglong2* __restrict__ q2a0 = &s2a[(wid * 2 + 0) * NP];
    const ulonglong2* __restrict__ q2a1 = &s2a[(wid * 2 + 1) * NP];
    const ulonglong2* __restrict__ q2b0 = &s2b[(wid * 2 + 0) * NP];
    const ulonglong2* __restrict__ q2b1 = &s2b[(wid * 2 + 1) * NP];

    u64 p2x[2], p2y[2], p2z[2], p2w[2];
    {
        const ulonglong2 va0 = q2a0[lane], vb0 = q2b0[lane];
        const ulonglong2 va1 = q2a1[lane], vb1 = q2b1[lane];
        p2x[0] = mul2(va0.x, neg2);  p2y[0] = mul2(va0.y, neg2);
        p2z[0] = mul2(vb0.x, neg2);  p2w[0] = vb0.y;
        p2x[1] = mul2(va1.x, neg2);  p2y[1] = mul2(va1.y, neg2);
        p2z[1] = mul2(vb1.x, neg2);  p2w[1] = vb1.y;
    }

    const float FLTMAX = 3.402823466e+38f;
    float m1aA[2], m1bA[2], m1aB[2], m1bB[2];   // dir-1 mins (lane = n)
    float m2aA[2], m2bA[2], m2aB[2], m2bB[2];   // dir-2 mins (lane = m)
    #pragma unroll
    for (int j = 0; j < 2; j++) {
        m1aA[j] = m1bA[j] = m1aB[j] = m1bB[j] = FLTMAX;
        m2aA[j] = m2bA[j] = m2aB[j] = m2bB[j] = FLTMAX;
    }

    #pragma unroll 4
    for (int m = 0; m < NP; m++) {
        const float4 rA = s1A[m];                 // broadcast LDS.128
        const float4 rB = s1B[m];                 // broadcast LDS.128
        const u64 rxA = pack2(rA.x, rA.x), ryA = pack2(rA.y, rA.y);
        const u64 rzA = pack2(rA.z, rA.z), rwA = pack2(rA.w, rA.w);
        const u64 rxB = pack2(rB.x, rB.x), ryB = pack2(rB.y, rB.y);
        const u64 rzB = pack2(rB.z, rB.z), rwB = pack2(rB.w, rB.w);

        const ulonglong2 va0 = q2a0[m], vb0 = q2b0[m];   // broadcast LDS.128 x2
        const ulonglong2 va1 = q2a1[m], vb1 = q2b1[m];   // broadcast LDS.128 x2

        // ---- pair 0 ----
        {
            const float2 d1A = unpack2(fma2(pxA, va0.x, fma2(pyA, va0.y, fma2(pzA, vb0.x, vb0.y))));
            m1aA[0] = fminf(m1aA[0], d1A.x);  m1bA[0] = fminf(m1bA[0], d1A.y);
            const float2 d1B = unpack2(fma2(pxB, va0.x, fma2(pyB, va0.y, fma2(pzB, vb0.x, vb0.y))));
            m1aB[0] = fminf(m1aB[0], d1B.x);  m1bB[0] = fminf(m1bB[0], d1B.y);
            const float2 d2A = unpack2(fma2(p2x[0], rxA, fma2(p2y[0], ryA, fma2(p2z[0], rzA, rwA))));
            m2aA[0] = fminf(m2aA[0], d2A.x);  m2bA[0] = fminf(m2bA[0], d2A.y);
            const float2 d2B = unpack2(fma2(p2x[0], rxB, fma2(p2y[0], ryB, fma2(p2z[0], rzB, rwB))));
            m2aB[0] = fminf(m2aB[0], d2B.x);  m2bB[0] = fminf(m2bB[0], d2B.y);
        }
        // ---- pair 1 ----
        {
            const float2 d1A = unpack2(fma2(pxA, va1.x, fma2(pyA, va1.y, fma2(pzA, vb1.x, vb1.y))));
            m1aA[1] = fminf(m1aA[1], d1A.x);  m1bA[1] = fminf(m1bA[1], d1A.y);
            const float2 d1B = unpack2(fma2(pxB, va1.x, fma2(pyB, va1.y, fma2(pzB, vb1.x, vb1.y))));
            m1aB[1] = fminf(m1aB[1], d1B.x);  m1bB[1] = fminf(m1bB[1], d1B.y);
            const float2 d2A = unpack2(fma2(p2x[1], rxA, fma2(p2y[1], ryA, fma2(p2z[1], rzA, rwA))));
            m2aA[1] = fminf(m2aA[1], d2A.x);  m2bA[1] = fminf(m2bA[1], d2A.y);
            const float2 d2B = unpack2(fma2(p2x[1], rxB, fma2(p2y[1], ryB, fma2(p2z[1], rzB, rwB))));
            m2aB[1] = fminf(m2aB[1], d2B.x);  m2bB[1] = fminf(m2bB[1], d2B.y);
        }
    }

    // Finalize: fold lane-constant norms, butterfly-sum, store.
    const int g1A = b * 64 + 2 * gp;
    #pragma unroll
    for (int j = 0; j < 2; j++) {
        const float2 w2 = unpack2(p2w[j]);
        float vaA = (m1aA[j] + p1A.w) + (m2aA[j] + w2.x);
        float vbA = (m1bA[j] + p1A.w) + (m2bA[j] + w2.y);
        float vaB = (m1aB[j] + p1B.w) + (m2aB[j] + w2.x);
        float vbB = (m1bB[j] + p1B.w) + (m2bB[j] + w2.y);
        #pragma unroll
        for (int o = 16; o; o >>= 1) {
            vaA += __shfl_xor_sync(0xffffffffu, vaA, o);
            vbA += __shfl_xor_sync(0xffffffffu, vbA, o);
            vaB += __shfl_xor_sync(0xffffffffu, vaB, o);
            vbB += __shfl_xor_sync(0xffffffffu, vbB, o);
        }
        if (lane == 0) {
            const int g2 = half * 32 + (wid * 2 + j) * 2;
            out[(size_t)g1A * 64 + g2]            = vaA * (1.0f / 32.0f);
            out[(size_t)g1A * 64 + g2 + 1]        = vbA * (1.0f / 32.0f);
            out[(size_t)(g1A + 1) * 64 + g2]      = vaB * (1.0f / 32.0f);
            out[(size_t)(g1A + 1) * 64 + g2 + 1]  = vbB * (1.0f / 32.0f);
        }
    }
}

extern "C" void kernel_launch(void* const* d_in, const int* in_sizes, int n_in,
                              void* d_out, int out_size) {
    const float* x1  = (const float*)d_in[0];  // xyz1_matrix [32,64,32,3]
    const float* x2  = (const float*)d_in[1];  // xyz2_matrix [32,64,32,3]
    float*       out = (float*)d_out;          // [32,64,64]
    chamfer_matrix_kernel<<<32 * 64, 256>>>(x1, x2, out);
}

// round 7
// speedup vs baseline: 1.1412x; 1.1412x over previous
#include <cuda_runtime.h>
#include <cuda_bf16.h>

// Chamfer distance matrix, B=32, G=64, N=32, C=3.
// R7: single-evaluation tile + integer redux for column mins.
// Each warp computes each 32x32 distance tile ONCE (lane = n, packed f32x2
// over g2-group pairs). Full d (both norms folded in-loop) is >= 0, so its
// bit pattern compares as s32 exactly like the float: dir-2 column min uses
// __reduce_min_sync (REDUX.SYNC.MIN.S32, sm_80+) instead of re-evaluating
// the tile with swapped roles. dir-1 row min stays lane-local fminf.
// Tiling as R3: block = (b, g1-pair), warp = 4 g2-pairs; 3 CTAs/SM.

#define NP 32

typedef unsigned long long u64;

static __device__ __forceinline__ u64 pack2(float lo, float hi) {
    u64 r; asm("mov.b64 %0, {%1, %2};" : "=l"(r) : "f"(lo), "f"(hi)); return r;
}
static __device__ __forceinline__ float2 unpack2(u64 v) {
    float2 f; asm("mov.b64 {%0, %1}, %2;" : "=f"(f.x), "=f"(f.y) : "l"(v)); return f;
}
static __device__ __forceinline__ u64 fma2(u64 a, u64 b, u64 c) {
    u64 d; asm("fma.rn.f32x2 %0, %1, %2, %3;" : "=l"(d) : "l"(a), "l"(b), "l"(c)); return d;
}
static __device__ __forceinline__ u64 add2(u64 a, u64 b) {
    u64 d; asm("add.rn.f32x2 %0, %1, %2;" : "=l"(d) : "l"(a), "l"(b)); return d;
}
// Warp-wide float min for non-negative floats via s32 redux on the bits.
static __device__ __forceinline__ float warp_min_pos(float v) {
    return __int_as_float(__reduce_min_sync(0xffffffffu, __float_as_int(v)));
}

__global__ __launch_bounds__(256, 3)
void chamfer_matrix_kernel(const float* __restrict__ x1,
                           const float* __restrict__ x2,
                           float* __restrict__ out)
{
    // Pair-packed x2 slice: for g2-pair p, point m:
    //   s2a[p*32+m] = {a.x,b.x, a.y,b.y}; s2b[p*32+m] = {a.z,b.z, a.w,b.w}
    __shared__ ulonglong2 s2a[32 * NP];     // 16 KB
    __shared__ ulonglong2 s2b[32 * NP];     // 16 KB

    const int blk = blockIdx.x;        // b*32 + g1pair
    const int b   = blk >> 5;
    const int gp  = blk & 31;          // g1 pair -> groups 2gp, 2gp+1
    const int tid = threadIdx.x;

    // Stage x2[b]: 2048 points, pre-packed pairwise.
    const float* __restrict__ x2b = x2 + (size_t)b * 64 * NP * 3;
    #pragma unroll
    for (int i = tid; i < 64 * NP; i += 256) {
        const float X = x2b[i * 3 + 0];
        const float Y = x2b[i * 3 + 1];
        const float Z = x2b[i * 3 + 2];
        const float W = fmaf(X, X, fmaf(Y, Y, Z * Z));
        const int g = i >> 5, m = i & 31;
        const int p = g >> 1, h = g & 1;
        float* da = (float*)&s2a[p * NP + m];
        float* db = (float*)&s2b[p * NP + m];
        da[0 + h] = X;  da[2 + h] = Y;
        db[0 + h] = Z;  db[2 + h] = W;
    }

    const int wid  = tid >> 5;
    const int lane = tid & 31;

    // Lane-own x1 points (groups 2gp, 2gp+1) straight from gmem (L2-hot).
    const int g1A = b * 64 + 2 * gp;
    const float* __restrict__ pA = x1 + (size_t)(g1A * NP + lane) * 3;
    const float* __restrict__ pB = pA + (size_t)NP * 3;
    const float xA = pA[0], yA = pA[1], zA = pA[2];
    const float xB = pB[0], yB = pB[1], zB = pB[2];
    const float wAs = fmaf(xA, xA, fmaf(yA, yA, zA * zA));
    const float wBs = fmaf(xB, xB, fmaf(yB, yB, zB * zB));

    // Pre-scaled (-2x) splats; norm splats for the in-loop bias.
    const u64 pxA = pack2(-2.0f * xA, -2.0f * xA);
    const u64 pyA = pack2(-2.0f * yA, -2.0f * yA);
    const u64 pzA = pack2(-2.0f * zA, -2.0f * zA);
    const u64 pxB = pack2(-2.0f * xB, -2.0f * xB);
    const u64 pyB = pack2(-2.0f * yB, -2.0f * yB);
    const u64 pzB = pack2(-2.0f * zB, -2.0f * zB);
    const u64 wA  = pack2(wAs, wAs);
    const u64 wB  = pack2(wBs, wBs);

    __syncthreads();

    const float FLTMAX = 3.402823466e+38f;
    float m1A0[4], m1A1[4], m1B0[4], m1B1[4];   // dir-1 row mins (lane = n)
    float sA0[4],  sA1[4],  sB0[4],  sB1[4];    // dir-2 colmin sums (uniform)
    #pragma unroll
    for (int j = 0; j < 4; j++) {
        m1A0[j] = m1A1[j] = m1B0[j] = m1B1[j] = FLTMAX;
        sA0[j] = sA1[j] = sB0[j] = sB1[j] = 0.0f;
    }

    const ulonglong2* __restrict__ q2a = &s2a[wid * 4 * NP];
    const ulonglong2* __restrict__ q2b = &s2b[wid * 4 * NP];

    #pragma unroll 4
    for (int m = 0; m < NP; m++) {
        #pragma unroll
        for (int j = 0; j < 4; j++) {
            const ulonglong2 va = q2a[j * NP + m];   // {ax,bx, ay,by}
            const ulonglong2 vb = q2b[j * NP + m];   // {az,bz, aw,bw}
            // Full distance d[n][m] (>= 0), both g2 groups of the pair:
            const u64 dA = fma2(pxA, va.x, fma2(pyA, va.y, fma2(pzA, vb.x, add2(vb.y, wA))));
            const u64 dB = fma2(pxB, va.x, fma2(pyB, va.y, fma2(pzB, vb.x, add2(vb.y, wB))));
            const float2 fA = unpack2(dA);
            const float2 fB = unpack2(dB);
            // dir-1: lane-local running min over m.
            m1A0[j] = fminf(m1A0[j], fA.x);  m1A1[j] = fminf(m1A1[j], fA.y);
            m1B0[j] = fminf(m1B0[j], fB.x);  m1B1[j] = fminf(m1B1[j], fB.y);
            // dir-2: exact warp-wide min over n (s32 redux on bits), sum over m.
            sA0[j] += warp_min_pos(fA.x);    sA1[j] += warp_min_pos(fA.y);
            sB0[j] += warp_min_pos(fB.x);    sB1[j] += warp_min_pos(fB.y);
        }
    }

    // Epilogue: packed butterfly-sum of the dir-1 mins, add dir-2 sums.
    #pragma unroll
    for (int j = 0; j < 4; j++) {
        u64 vA = pack2(m1A0[j], m1A1[j]);
        u64 vB = pack2(m1B0[j], m1B1[j]);
        #pragma unroll
        for (int o = 16; o; o >>= 1) {
            vA = add2(vA, __shfl_xor_sync(0xffffffffu, vA, o));
            vB = add2(vB, __shfl_xor_sync(0xffffffffu, vB, o));
        }
        if (lane == 0) {
            const float2 rA = unpack2(vA);
            const float2 rB = unpack2(vB);
            const int g2 = (wid * 4 + j) * 2;
            out[(size_t)g1A * 64 + g2]           = (rA.x + sA0[j]) * (1.0f / 32.0f);
            out[(size_t)g1A * 64 + g2 + 1]       = (rA.y + sA1[j]) * (1.0f / 32.0f);
            out[(size_t)(g1A + 1) * 64 + g2]     = (rB.x + sB0[j]) * (1.0f / 32.0f);
            out[(size_t)(g1A + 1) * 64 + g2 + 1] = (rB.y + sB1[j]) * (1.0f / 32.0f);
        }
    }
}

extern "C" void kernel_launch(void* const* d_in, const int* in_sizes, int n_in,
                              void* d_out, int out_size) {
    const float* x1  = (const float*)d_in[0];  // xyz1_matrix [32,64,32,3]
    const float* x2  = (const float*)d_in[1];  // xyz2_matrix [32,64,32,3]
    float*       out = (float*)d_out;          // [32,64,64]
    chamfer_matrix_kernel<<<32 * 32, 256>>>(x1, x2, out);
}

// round 8
// speedup vs baseline: 1.2597x; 1.1039x over previous
#include <cuda_runtime.h>
#include <cuda_bf16.h>

// Chamfer distance matrix, B=32, G=64, N=32, C=3.
// R8: R7 single-evaluation + s32-redux structure, re-tiled for occupancy.
// Warp tile halved to j=2 g2-pairs (per-combo issue cost is j-invariant here:
// LDS/combo, packed-fma/combo, scalar trio/combo all unchanged), shrinking
// live registers so __launch_bounds__(256,4) holds -> 32 warps/SM.
// Block = (b, g1-pair, g2-half): grid 2048, smem 16KB.

#define NP 32

typedef unsigned long long u64;

static __device__ __forceinline__ u64 pack2(float lo, float hi) {
    u64 r; asm("mov.b64 %0, {%1, %2};" : "=l"(r) : "f"(lo), "f"(hi)); return r;
}
static __device__ __forceinline__ float2 unpack2(u64 v) {
    float2 f; asm("mov.b64 {%0, %1}, %2;" : "=f"(f.x), "=f"(f.y) : "l"(v)); return f;
}
static __device__ __forceinline__ u64 fma2(u64 a, u64 b, u64 c) {
    u64 d; asm("fma.rn.f32x2 %0, %1, %2, %3;" : "=l"(d) : "l"(a), "l"(b), "l"(c)); return d;
}
static __device__ __forceinline__ u64 add2(u64 a, u64 b) {
    u64 d; asm("add.rn.f32x2 %0, %1, %2;" : "=l"(d) : "l"(a), "l"(b)); return d;
}
// Warp-wide float min for non-negative floats via s32 redux on the bits.
static __device__ __forceinline__ float warp_min_pos(float v) {
    return __int_as_float(__reduce_min_sync(0xffffffffu, __float_as_int(v)));
}

__global__ __launch_bounds__(256, 4)
void chamfer_matrix_kernel(const float* __restrict__ x1,
                           const float* __restrict__ x2,
                           float* __restrict__ out)
{
    // Pair-packed x2 subset (this block's g2-half = 16 pairs):
    //   s2a[p*32+m] = {a.x,b.x, a.y,b.y}; s2b[p*32+m] = {a.z,b.z, a.w,b.w}
    __shared__ ulonglong2 s2a[16 * NP];     // 8 KB
    __shared__ ulonglong2 s2b[16 * NP];     // 8 KB

    const int blk  = blockIdx.x;        // b*64 + gp*2 + half
    const int b    = blk >> 6;
    const int gp   = (blk >> 1) & 31;   // g1 pair -> groups 2gp, 2gp+1
    const int half = blk & 1;           // g2 groups [half*32, half*32+32)
    const int tid  = threadIdx.x;

    // Stage this block's 1024 x2 points, pre-packed pairwise.
    const float* __restrict__ x2b = x2 + (size_t)(b * 64 + half * 32) * NP * 3;
    #pragma unroll
    for (int i = tid; i < 32 * NP; i += 256) {
        const float X = x2b[i * 3 + 0];
        const float Y = x2b[i * 3 + 1];
        const float Z = x2b[i * 3 + 2];
        const float W = fmaf(X, X, fmaf(Y, Y, Z * Z));
        const int g = i >> 5, m = i & 31;       // local group 0..31
        const int p = g >> 1, h = g & 1;        // local pair 0..15
        float* da = (float*)&s2a[p * NP + m];
        float* db = (float*)&s2b[p * NP + m];
        da[0 + h] = X;  da[2 + h] = Y;
        db[0 + h] = Z;  db[2 + h] = W;
    }

    const int wid  = tid >> 5;
    const int lane = tid & 31;

    // Lane-own x1 points (groups 2gp, 2gp+1) straight from gmem (L2-hot).
    const int g1A = b * 64 + 2 * gp;
    const float* __restrict__ pA = x1 + (size_t)(g1A * NP + lane) * 3;
    const float* __restrict__ pB = pA + (size_t)NP * 3;
    const float xA = pA[0], yA = pA[1], zA = pA[2];
    const float xB = pB[0], yB = pB[1], zB = pB[2];
    const float wAs = fmaf(xA, xA, fmaf(yA, yA, zA * zA));
    const float wBs = fmaf(xB, xB, fmaf(yB, yB, zB * zB));

    // Pre-scaled (-2x) splats; norm splats for the in-loop bias.
    const u64 pxA = pack2(-2.0f * xA, -2.0f * xA);
    const u64 pyA = pack2(-2.0f * yA, -2.0f * yA);
    const u64 pzA = pack2(-2.0f * zA, -2.0f * zA);
    const u64 pxB = pack2(-2.0f * xB, -2.0f * xB);
    const u64 pyB = pack2(-2.0f * yB, -2.0f * yB);
    const u64 pzB = pack2(-2.0f * zB, -2.0f * zB);
    const u64 wA  = pack2(wAs, wAs);
    const u64 wB  = pack2(wBs, wBs);

    __syncthreads();

    const float FLTMAX = 3.402823466e+38f;
    float m1A0[2], m1A1[2], m1B0[2], m1B1[2];   // dir-1 row mins (lane = n)
    float sA0[2],  sA1[2],  sB0[2],  sB1[2];    // dir-2 colmin sums (uniform)
    #pragma unroll
    for (int j = 0; j < 2; j++) {
        m1A0[j] = m1A1[j] = m1B0[j] = m1B1[j] = FLTMAX;
        sA0[j] = sA1[j] = sB0[j] = sB1[j] = 0.0f;
    }

    const ulonglong2* __restrict__ q2a = &s2a[wid * 2 * NP];
    const ulonglong2* __restrict__ q2b = &s2b[wid * 2 * NP];

    #pragma unroll 4
    for (int m = 0; m < NP; m++) {
        #pragma unroll
        for (int j = 0; j < 2; j++) {
            const ulonglong2 va = q2a[j * NP + m];   // {ax,bx, ay,by}
            const ulonglong2 vb = q2b[j * NP + m];   // {az,bz, aw,bw}
            // Full distance d[n][m] (>= 0), both g2 groups of the pair:
            const u64 dA = fma2(pxA, va.x, fma2(pyA, va.y, fma2(pzA, vb.x, add2(vb.y, wA))));
            const u64 dB = fma2(pxB, va.x, fma2(pyB, va.y, fma2(pzB, vb.x, add2(vb.y, wB))));
            const float2 fA = unpack2(dA);
            const float2 fB = unpack2(dB);
            // dir-1: lane-local running min over m.
            m1A0[j] = fminf(m1A0[j], fA.x);  m1A1[j] = fminf(m1A1[j], fA.y);
            m1B0[j] = fminf(m1B0[j], fB.x);  m1B1[j] = fminf(m1B1[j], fB.y);
            // dir-2: exact warp-wide min over n (s32 redux on bits), sum over m.
            sA0[j] += warp_min_pos(fA.x);    sA1[j] += warp_min_pos(fA.y);
            sB0[j] += warp_min_pos(fB.x);    sB1[j] += warp_min_pos(fB.y);
        }
    }

    // Epilogue: packed butterfly-sum of the dir-1 mins, add dir-2 sums.
    #pragma unroll
    for (int j = 0; j < 2; j++) {
        u64 vA = pack2(m1A0[j], m1A1[j]);
        u64 vB = pack2(m1B0[j], m1B1[j]);
        #pragma unroll
        for (int o = 16; o; o >>= 1) {
            vA = add2(vA, __shfl_xor_sync(0xffffffffu, vA, o));
            vB = add2(vB, __shfl_xor_sync(0xffffffffu, vB, o));
        }
        if (lane == 0) {
            const float2 rA = unpack2(vA);
            const float2 rB = unpack2(vB);
            const int g2 = half * 32 + (wid * 2 + j) * 2;
            out[(size_t)g1A * 64 + g2]           = (rA.x + sA0[j]) * (1.0f / 32.0f);
            out[(size_t)g1A * 64 + g2 + 1]       = (rA.y + sA1[j]) * (1.0f / 32.0f);
            out[(size_t)(g1A + 1) * 64 + g2]     = (rB.x + sB0[j]) * (1.0f / 32.0f);
            out[(size_t)(g1A + 1) * 64 + g2 + 1] = (rB.y + sB1[j]) * (1.0f / 32.0f);
        }
    }
}

extern "C" void kernel_launch(void* const* d_in, const int* in_sizes, int n_in,
                              void* d_out, int out_size) {
    const float* x1  = (const float*)d_in[0];  // xyz1_matrix [32,64,32,3]
    const float* x2  = (const float*)d_in[1];  // xyz2_matrix [32,64,32,3]
    float*       out = (float*)d_out;          // [32,64,64]
    chamfer_matrix_kernel<<<32 * 64, 256>>>(x1, x2, out);
}